// round 1
// baseline (speedup 1.0000x reference)
#include <cuda_runtime.h>
#include <math.h>

#define Bb   256
#define Tt   100
#define NIN  64
#define Hh   1024
#define G4   4096   // 4*H

// ---------------- device scratch (allocation-free: __device__ globals) ------
__device__ float g_gin[(size_t)Bb * Tt * G4];   // per-layer precomputed input gates, [t*B+b, 4H]
__device__ float g_act0[(size_t)Bb * Tt * Hh];  // layer activation ping
__device__ float g_act1[(size_t)Bb * Tt * Hh];  // layer activation pong
__device__ float g_h[2][Bb * Hh];               // recurrent h ping-pong
__device__ float g_c[Bb * Hh];                  // cell state (in-place)
__device__ float g_xT[(size_t)Bb * Tt * NIN];   // x transposed to [t*B+b, NIN]

// ---------------- kernels ---------------------------------------------------

// x[B,T,NIN] -> xT[(t*B+b), NIN]
__global__ void transpose_x_kernel(const float* __restrict__ x) {
    int idx = blockIdx.x * blockDim.x + threadIdx.x;
    if (idx < Bb * Tt * NIN) {
        int k = idx % NIN;
        int m = idx / NIN;          // m = t*B + b
        int b = m % Bb;
        int t = m / Bb;
        g_xT[idx] = x[((size_t)b * Tt + t) * NIN + k];
    }
}

// zero h[0] and c
__global__ void zero_state_kernel(float* __restrict__ h0, float* __restrict__ c) {
    int i = blockIdx.x * blockDim.x + threadIdx.x;
    if (i < Bb * Hh) { h0[i] = 0.f; c[i] = 0.f; }
}

__global__ void copy_c_kernel(const float* __restrict__ c, float* __restrict__ dst) {
    int i = blockIdx.x * blockDim.x + threadIdx.x;
    if (i < Bb * Hh) dst[i] = c[i];
}

// Big input GEMM: gin[m, n] = sum_k A[m,k] * W[n,k] + bih[n] + bhh[n]
// A: [M=B*T, K] row-major, W: [4H, K] row-major. Tile 64x64, BK=16, 256 thr, 4x4/thread.
__global__ void input_gemm_kernel(const float* __restrict__ A, int K,
                                  const float* __restrict__ W,
                                  const float* __restrict__ bih,
                                  const float* __restrict__ bhh) {
    __shared__ __align__(16) float As[16][64];
    __shared__ __align__(16) float Ws[16][64];

    int tid = threadIdx.x;
    int m0 = blockIdx.y * 64;
    int n0 = blockIdx.x * 64;

    float acc[4][4];
    #pragma unroll
    for (int i = 0; i < 4; i++)
        #pragma unroll
        for (int j = 0; j < 4; j++) acc[i][j] = 0.f;

    int lr = tid & 63;   // row within tile
    int lk = tid >> 6;   // 0..3 -> k quad
    int tr = tid >> 4;   // 0..15
    int tc = tid & 15;   // 0..15

    for (int k0 = 0; k0 < K; k0 += 16) {
        float4 va = *(const float4*)&A[(size_t)(m0 + lr) * K + k0 + lk * 4];
        float4 vw = *(const float4*)&W[(size_t)(n0 + lr) * K + k0 + lk * 4];
        As[lk * 4 + 0][lr] = va.x; As[lk * 4 + 1][lr] = va.y;
        As[lk * 4 + 2][lr] = va.z; As[lk * 4 + 3][lr] = va.w;
        Ws[lk * 4 + 0][lr] = vw.x; Ws[lk * 4 + 1][lr] = vw.y;
        Ws[lk * 4 + 2][lr] = vw.z; Ws[lk * 4 + 3][lr] = vw.w;
        __syncthreads();
        #pragma unroll
        for (int k = 0; k < 16; k++) {
            float4 a = *(const float4*)&As[k][tr * 4];
            float4 b = *(const float4*)&Ws[k][tc * 4];
            acc[0][0] += a.x * b.x; acc[0][1] += a.x * b.y; acc[0][2] += a.x * b.z; acc[0][3] += a.x * b.w;
            acc[1][0] += a.y * b.x; acc[1][1] += a.y * b.y; acc[1][2] += a.y * b.z; acc[1][3] += a.y * b.w;
            acc[2][0] += a.z * b.x; acc[2][1] += a.z * b.y; acc[2][2] += a.z * b.z; acc[2][3] += a.z * b.w;
            acc[3][0] += a.w * b.x; acc[3][1] += a.w * b.y; acc[3][2] += a.w * b.z; acc[3][3] += a.w * b.w;
        }
        __syncthreads();
    }

    int n = n0 + tc * 4;
    float4 b1 = *(const float4*)&bih[n];
    float4 b2 = *(const float4*)&bhh[n];
    float4 bias = make_float4(b1.x + b2.x, b1.y + b2.y, b1.z + b2.z, b1.w + b2.w);
    #pragma unroll
    for (int i = 0; i < 4; i++) {
        int m = m0 + tr * 4 + i;
        float4 o = make_float4(acc[i][0] + bias.x, acc[i][1] + bias.y,
                               acc[i][2] + bias.z, acc[i][3] + bias.w);
        *(float4*)&g_gin[(size_t)m * G4 + n] = o;
    }
}

__device__ __forceinline__ float sigmoidf_(float v) { return 1.f / (1.f + expf(-v)); }

// One timestep of one layer: gates = gin_t + hin @ Whh^T, fused LSTM cell epilogue.
// Tile: 64 (batch) x 32 (h) per CTA; per thread 4b x 2h, 4 gates -> 32 acc.
// grid = (H/32, B/64) = (32, 4) = 128 CTAs, 256 threads.
__global__ void lstm_step_kernel(const float* __restrict__ hin,
                                 float* __restrict__ hout,
                                 const float* __restrict__ Whh,
                                 const float* __restrict__ gin_t,   // + t*B*4H already
                                 float* __restrict__ c,
                                 float* __restrict__ act_out,       // [t*B+b, H] or null
                                 float* __restrict__ out_bth,       // [b*T+t, H] or null
                                 int t) {
    __shared__ __align__(16) float As[16][64];       // [k][b]
    __shared__ __align__(16) float Ws[4][16][32];    // [gate][k][h]

    int tid = threadIdx.x;
    int hb = blockIdx.x * 32;
    int mb = blockIdx.y * 64;

    float acc[4][4][2];
    #pragma unroll
    for (int g = 0; g < 4; g++)
        #pragma unroll
        for (int i = 0; i < 4; i++) { acc[g][i][0] = 0.f; acc[g][i][1] = 0.f; }

    int ab = tid & 63;                 // batch row for A load
    int ak = tid >> 6;                 // 0..3 k-quad for A load
    int wh = tid & 31;                 // h row for W load
    int wrest = tid >> 5;              // 0..7
    int wg = wrest >> 1;               // gate 0..3
    int wk0 = (wrest & 1) * 2;         // k-quad pair base
    int tr = tid >> 4;                 // 0..15 (4 b each)
    int tc = tid & 15;                 // 0..15 (2 h each)

    for (int k0 = 0; k0 < Hh; k0 += 16) {
        {
            float4 v = *(const float4*)&hin[(size_t)(mb + ab) * Hh + k0 + ak * 4];
            As[ak * 4 + 0][ab] = v.x; As[ak * 4 + 1][ab] = v.y;
            As[ak * 4 + 2][ab] = v.z; As[ak * 4 + 3][ab] = v.w;
        }
        #pragma unroll
        for (int q = 0; q < 2; q++) {
            int kq = wk0 + q;
            float4 v = *(const float4*)&Whh[(size_t)(wg * Hh + hb + wh) * Hh + k0 + kq * 4];
            Ws[wg][kq * 4 + 0][wh] = v.x; Ws[wg][kq * 4 + 1][wh] = v.y;
            Ws[wg][kq * 4 + 2][wh] = v.z; Ws[wg][kq * 4 + 3][wh] = v.w;
        }
        __syncthreads();
        #pragma unroll
        for (int k = 0; k < 16; k++) {
            float4 a = *(const float4*)&As[k][tr * 4];
            #pragma unroll
            for (int g = 0; g < 4; g++) {
                float w0 = Ws[g][k][tc * 2];
                float w1 = Ws[g][k][tc * 2 + 1];
                acc[g][0][0] += a.x * w0; acc[g][0][1] += a.x * w1;
                acc[g][1][0] += a.y * w0; acc[g][1][1] += a.y * w1;
                acc[g][2][0] += a.z * w0; acc[g][2][1] += a.z * w1;
                acc[g][3][0] += a.w * w0; acc[g][3][1] += a.w * w1;
            }
        }
        __syncthreads();
    }

    // fused LSTM cell epilogue
    #pragma unroll
    for (int i = 0; i < 4; i++) {
        int b = mb + tr * 4 + i;
        const float* gr = gin_t + (size_t)b * G4;
        #pragma unroll
        for (int j = 0; j < 2; j++) {
            int h = hb + tc * 2 + j;
            float xi = acc[0][i][j] + gr[h];
            float xf = acc[1][i][j] + gr[Hh + h];
            float xg = acc[2][i][j] + gr[2 * Hh + h];
            float xo = acc[3][i][j] + gr[3 * Hh + h];
            float ig = sigmoidf_(xi);
            float fg = sigmoidf_(xf);
            float gg = tanhf(xg);
            float og = sigmoidf_(xo);
            size_t idx = (size_t)b * Hh + h;
            float cn = fg * c[idx] + ig * gg;
            float hn = og * tanhf(cn);
            c[idx]    = cn;
            hout[idx] = hn;
            if (act_out) act_out[((size_t)t * Bb + b) * Hh + h] = hn;
            if (out_bth) out_bth[((size_t)b * Tt + t) * Hh + h] = hn;
        }
    }
}

// ---------------- host launcher ---------------------------------------------
extern "C" void kernel_launch(void* const* d_in, const int* in_sizes, int n_in,
                              void* d_out, int out_size) {
    const float* x = (const float*)d_in[0];
    const float* Wih[4] = {(const float*)d_in[1], (const float*)d_in[5],
                           (const float*)d_in[9], (const float*)d_in[13]};
    const float* Whh[4] = {(const float*)d_in[2], (const float*)d_in[6],
                           (const float*)d_in[10], (const float*)d_in[14]};
    const float* bih[4] = {(const float*)d_in[3], (const float*)d_in[7],
                           (const float*)d_in[11], (const float*)d_in[15]};
    const float* bhh[4] = {(const float*)d_in[4], (const float*)d_in[8],
                           (const float*)d_in[12], (const float*)d_in[16]};
    float* out = (float*)d_out;

    float *gin, *act0, *act1, *hb, *c, *xT;
    cudaGetSymbolAddress((void**)&gin,  g_gin);
    cudaGetSymbolAddress((void**)&act0, g_act0);
    cudaGetSymbolAddress((void**)&act1, g_act1);
    cudaGetSymbolAddress((void**)&hb,   g_h);
    cudaGetSymbolAddress((void**)&c,    g_c);
    cudaGetSymbolAddress((void**)&xT,   g_xT);
    float* hbuf[2] = {hb, hb + Bb * Hh};

    transpose_x_kernel<<<(Bb * Tt * NIN + 255) / 256, 256>>>(x);

    const float* acts_in[4] = {xT, act0, act1, act0};
    float*       acts_out[4] = {act0, act1, act0, nullptr};
    int          Ks[4] = {NIN, Hh, Hh, Hh};

    for (int L = 0; L < 4; L++) {
        dim3 ggrid(G4 / 64, (Bb * Tt) / 64);
        input_gemm_kernel<<<ggrid, 256>>>(acts_in[L], Ks[L], Wih[L], bih[L], bhh[L]);

        zero_state_kernel<<<(Bb * Hh + 255) / 256, 256>>>(hbuf[0], c);

        dim3 rgrid(Hh / 32, Bb / 64);
        for (int t = 0; t < Tt; t++) {
            lstm_step_kernel<<<rgrid, 256>>>(hbuf[t & 1], hbuf[(t + 1) & 1],
                                             Whh[L], gin + (size_t)t * Bb * G4, c,
                                             acts_out[L], (L == 3) ? out : nullptr, t);
        }
    }

    copy_c_kernel<<<(Bb * Hh + 255) / 256, 256>>>(c, out + (size_t)Bb * Tt * Hh);
}

// round 5
// speedup vs baseline: 2.9509x; 2.9509x over previous
#include <cuda_runtime.h>
#include <cuda_bf16.h>
#include <math.h>
#include <stdint.h>

#define Bb 256
#define Tt 100
#define NINp 64
#define Hh 1024
#define G4 4096
#define MTOT (Bb*Tt)
#define K3MAX (3*Hh)

// ------------------------- device scratch ----------------------------------
__device__ __align__(128) __nv_bfloat16 g_WihP[4][(size_t)G4 * K3MAX];
__device__ __align__(128) __nv_bfloat16 g_WhhP[4][(size_t)G4 * K3MAX];
__device__ __align__(128) float         g_biasP[4][G4];
__device__ __align__(128) float         g_gin[(size_t)MTOT * G4];
__device__ __align__(128) __nv_bfloat16 g_actAHi[(size_t)MTOT * Hh];
__device__ __align__(128) __nv_bfloat16 g_actALo[(size_t)MTOT * Hh];
__device__ __align__(128) __nv_bfloat16 g_actBHi[(size_t)MTOT * Hh];
__device__ __align__(128) __nv_bfloat16 g_actBLo[(size_t)MTOT * Hh];
__device__ __align__(128) __nv_bfloat16 g_xHi[(size_t)MTOT * NINp];
__device__ __align__(128) __nv_bfloat16 g_xLo[(size_t)MTOT * NINp];
__device__ __align__(128) __nv_bfloat16 g_zero[Bb * Hh];
__device__ __align__(128) float         g_cT[Hh * Bb];

// ------------------------- asm helpers -------------------------------------
__device__ __forceinline__ uint32_t smem_u32(const void* p) {
    uint32_t a;
    asm("{ .reg .u64 t; cvta.to.shared.u64 t, %1; cvt.u32.u64 %0, t; }" : "=r"(a) : "l"(p));
    return a;
}
#define CP16(s, g)  asm volatile("cp.async.cg.shared.global [%0], [%1], 16;" :: "r"(s), "l"(g) : "memory")
#define CP_COMMIT() asm volatile("cp.async.commit_group;" ::: "memory")
#define CP_WAIT1()  asm volatile("cp.async.wait_group 1;" ::: "memory")
#define CP_WAIT0()  asm volatile("cp.async.wait_group 0;" ::: "memory")
#define LDSM_X4(r, addr) asm volatile( \
    "ldmatrix.sync.aligned.m8n8.x4.shared.b16 {%0,%1,%2,%3}, [%4];" \
    : "=r"((r)[0]), "=r"((r)[1]), "=r"((r)[2]), "=r"((r)[3]) : "r"(addr))
#define MMA16816(d, a, b) asm volatile( \
    "mma.sync.aligned.m16n8k16.row.col.f32.bf16.bf16.f32 " \
    "{%0,%1,%2,%3}, {%4,%5,%6,%7}, {%8,%9}, {%0,%1,%2,%3};" \
    : "+f"((d)[0]), "+f"((d)[1]), "+f"((d)[2]), "+f"((d)[3]) \
    : "r"((a)[0]), "r"((a)[1]), "r"((a)[2]), "r"((a)[3]), "r"((b)[0]), "r"((b)[1]))

__device__ __forceinline__ float sigf(float x) { return 1.f / (1.f + __expf(-x)); }

// ------------------------- GEMM core ---------------------------------------
// C[BM=128 x BN] += Aprime[arow0.., 0..3K) * Wp[n0.., 0..3K)^T
// Aprime = [Ahi | Ahi | Alo] along K (served by loader), Wp stored plainly.
// BK=64 (128B rows, XOR-swizzled), 8 warps (2m x 4n), warp tile 64 x BN/4.
template<int BN>
__device__ __forceinline__ void load_stage(
    const __nv_bfloat16* __restrict__ Ahi, const __nv_bfloat16* __restrict__ Alo,
    int Korig, int arow0, const __nv_bfloat16* __restrict__ Wp, int n0,
    int it, uint32_t smA, uint32_t smB, int tid)
{
    int kglob = it << 6;
    int seg = kglob / Korig;                       // 0,1 -> hi ; 2 -> lo
    const __nv_bfloat16* Asrc = (seg < 2) ? Ahi : Alo;
    int koff = kglob - seg * Korig;
    int st = it & 1;
    uint32_t aBase = smA + st * 16384;
    uint32_t bBase = smB + st * (BN * 128);
    size_t K3 = (size_t)(3 * Korig);
    #pragma unroll
    for (int i = 0; i < 4; i++) {                  // A: 128 rows x 8 chunks
        int u = tid + (i << 8);
        int row = u >> 3, kc = u & 7;
        const void* g = (const void*)(Asrc + (size_t)(arow0 + row) * Korig + koff + kc * 8);
        uint32_t s = aBase + row * 128 + ((kc ^ (row & 7)) << 4);
        CP16(s, g);
    }
    #pragma unroll
    for (int i = 0; i < (BN >> 5); i++) {          // B: BN rows x 8 chunks
        int u = tid + (i << 8);
        int row = u >> 3, kc = u & 7;
        const void* g = (const void*)(Wp + (size_t)(n0 + row) * K3 + kglob + kc * 8);
        uint32_t s = bBase + row * 128 + ((kc ^ (row & 7)) << 4);
        CP16(s, g);
    }
}

template<int BN>
__device__ __forceinline__ void compute_stage(
    int st, uint32_t smA, uint32_t smB, int lane, int wm, int wn,
    float (&acc)[4][BN/32][4])
{
    uint32_t aBase = smA + st * 16384;
    uint32_t bBase = smB + st * (BN * 128);
    #pragma unroll
    for (int k16 = 0; k16 < 4; k16++) {
        uint32_t a[4][4];
        int kc = k16 * 2 + (lane >> 4);
        #pragma unroll
        for (int fm = 0; fm < 4; fm++) {
            int row = wm * 64 + fm * 16 + (lane & 15);
            uint32_t addr = aBase + row * 128 + ((kc ^ (row & 7)) << 4);
            LDSM_X4(a[fm], addr);
        }
        uint32_t b[BN/32][2];
        #pragma unroll
        for (int fp = 0; fp < BN/64; fp++) {
            int row = wn * (BN/4) + fp * 16 + (lane & 15);
            uint32_t addr = bBase + row * 128 + ((kc ^ (row & 7)) << 4);
            uint32_t r[4];
            LDSM_X4(r, addr);
            b[fp*2][0] = r[0]; b[fp*2+1][0] = r[1];
            b[fp*2][1] = r[2]; b[fp*2+1][1] = r[3];
        }
        #pragma unroll
        for (int fm = 0; fm < 4; fm++)
            #pragma unroll
            for (int fn = 0; fn < BN/32; fn++)
                MMA16816(acc[fm][fn], a[fm], b[fn]);
    }
}

template<int BN>
__device__ __forceinline__ void gemm_core(
    const __nv_bfloat16* __restrict__ Ahi, const __nv_bfloat16* __restrict__ Alo,
    int Korig, int arow0, const __nv_bfloat16* __restrict__ Wp, int n0,
    char* sm, float (&acc)[4][BN/32][4])
{
    const int tid = threadIdx.x;
    const int lane = tid & 31, wid = tid >> 5;
    const int wm = wid & 1, wn = wid >> 1;
    const uint32_t smA = smem_u32(sm);
    const uint32_t smB = smA + 32768;

    #pragma unroll
    for (int fm = 0; fm < 4; fm++)
        #pragma unroll
        for (int fn = 0; fn < BN/32; fn++)
            #pragma unroll
            for (int i = 0; i < 4; i++) acc[fm][fn][i] = 0.f;

    const int NIT = (3 * Korig) >> 6;
    load_stage<BN>(Ahi, Alo, Korig, arow0, Wp, n0, 0, smA, smB, tid);
    CP_COMMIT();
    #pragma unroll 1
    for (int it = 0; it < NIT; it++) {
        if (it + 1 < NIT) {
            load_stage<BN>(Ahi, Alo, Korig, arow0, Wp, n0, it + 1, smA, smB, tid);
            CP_COMMIT();
            CP_WAIT1();
        } else {
            CP_WAIT0();
        }
        __syncthreads();
        compute_stage<BN>(it & 1, smA, smB, lane, wm, wn, acc);
        __syncthreads();
    }
}

// ------------------------- input GEMM --------------------------------------
__global__ void __launch_bounds__(256) k_gemm_in(
    const __nv_bfloat16* __restrict__ Ahi, const __nv_bfloat16* __restrict__ Alo, int Korig,
    const __nv_bfloat16* __restrict__ Wp, const float* __restrict__ biasP,
    float* __restrict__ gin)
{
    extern __shared__ char raw[];
    char* sm = (char*)(((uintptr_t)raw + 1023) & ~(uintptr_t)1023);
    int n0 = blockIdx.x * 128, m0 = blockIdx.y * 128;
    float acc[4][4][4];
    gemm_core<128>(Ahi, Alo, Korig, m0, Wp, n0, sm, acc);

    int tid = threadIdx.x, lane = tid & 31, wid = tid >> 5, wm = wid & 1, wn = wid >> 1;
    #pragma unroll
    for (int fm = 0; fm < 4; fm++) {
        int r0 = m0 + wm * 64 + fm * 16 + (lane >> 2);
        #pragma unroll
        for (int fn = 0; fn < 4; fn++) {
            int cg = n0 + wn * 32 + fn * 8 + (lane & 3) * 2;
            float2 bs = *(const float2*)&biasP[cg];
            float2 v0 = make_float2(acc[fm][fn][0] + bs.x, acc[fm][fn][1] + bs.y);
            float2 v1 = make_float2(acc[fm][fn][2] + bs.x, acc[fm][fn][3] + bs.y);
            *(float2*)&gin[(size_t)r0 * G4 + cg] = v0;
            *(float2*)&gin[((size_t)r0 + 8) * G4 + cg] = v1;
        }
    }
}

// ------------------------- recurrent step ----------------------------------
__global__ void __launch_bounds__(256) k_step(
    const __nv_bfloat16* __restrict__ hHi, const __nv_bfloat16* __restrict__ hLo,
    const __nv_bfloat16* __restrict__ Wp,
    const float* __restrict__ gin, float* __restrict__ cT,
    __nv_bfloat16* __restrict__ aoHi, __nv_bfloat16* __restrict__ aoLo,
    float* __restrict__ outp, int t)
{
    extern __shared__ char raw[];
    char* sm = (char*)(((uintptr_t)raw + 1023) & ~(uintptr_t)1023);
    int n0 = blockIdx.x * 64, m0 = blockIdx.y * 128;
    float acc[4][2][4];
    gemm_core<64>(hHi, hLo, Hh, m0, Wp, n0, sm, acc);

    int tid = threadIdx.x, lane = tid & 31, wid = tid >> 5, wm = wid & 1, wn = wid >> 1;
    float* s_out = (float*)sm;                           // [128][16]
    __nv_bfloat16* s_hi = (__nv_bfloat16*)(sm + 8192);   // [128][16]
    __nv_bfloat16* s_lo = (__nv_bfloat16*)(sm + 12288);  // [128][16]
    int hb_cta = blockIdx.x * 16;

    #pragma unroll
    for (int fm = 0; fm < 4; fm++) {
        int rbase = wm * 64 + fm * 16 + (lane >> 2);
        #pragma unroll
        for (int fn = 0; fn < 2; fn++) {
            float d0 = acc[fm][fn][0], d1 = acc[fm][fn][1];
            float d2 = acc[fm][fn][2], d3 = acc[fm][fn][3];
            float p0 = __shfl_xor_sync(0xFFFFFFFFu, d0, 1);
            float p1 = __shfl_xor_sync(0xFFFFFFFFu, d1, 1);
            float p2 = __shfl_xor_sync(0xFFFFFFFFu, d2, 1);
            float p3 = __shfl_xor_sync(0xFFFFFFFFu, d3, 1);
            // even lane -> row rbase, has (i,f); odd lane -> row rbase+8, has (g,o)
            int r = rbase + ((lane & 1) ? 8 : 0);
            float xi, xf, xg, xo;
            if ((lane & 1) == 0) { xi = d0; xf = d1; xg = p0; xo = p1; }
            else                 { xi = p2; xf = p3; xg = d2; xo = d3; }
            int hl = wn * 4 + fn * 2 + ((lane & 3) >> 1);
            int b = m0 + r;
            const float* gr = gin + ((size_t)(t * Bb + b)) * G4 + n0 + hl * 4;
            float4 gv = *(const float4*)gr;
            xi += gv.x; xf += gv.y; xg += gv.z; xo += gv.w;
            float ig = sigf(xi), fg = sigf(xf), gg = tanhf(xg), og = sigf(xo);
            size_t ci = (size_t)(hb_cta + hl) * Bb + b;
            float cn = fg * cT[ci] + ig * gg;
            cT[ci] = cn;
            float hn = og * tanhf(cn);
            int si = r * 16 + hl;
            s_out[si] = hn;
            __nv_bfloat16 bh = __float2bfloat16(hn);
            s_hi[si] = bh;
            s_lo[si] = __float2bfloat16(hn - __bfloat162float(bh));
        }
    }
    __syncthreads();
    #pragma unroll
    for (int i = 0; i < 8; i++) {
        int u = tid + i * 256;
        int r = u >> 4, hl = u & 15;
        int b = m0 + r;
        size_t ai = ((size_t)(t * Bb + b)) * Hh + hb_cta + hl;
        aoHi[ai] = s_hi[u];
        aoLo[ai] = s_lo[u];
        if (outp) outp[((size_t)b * Tt + t) * Hh + hb_cta + hl] = s_out[u];
    }
}

// ------------------------- conversion / misc -------------------------------
__global__ void k_conv_w(const float* __restrict__ src, __nv_bfloat16* __restrict__ dst, int Korig) {
    int idx = blockIdx.x * blockDim.x + threadIdx.x;
    if (idx >= G4 * Korig) return;
    int n = idx / Korig, k = idx - n * Korig;
    int h = n >> 2, g = n & 3;
    float v = src[(size_t)(g * Hh + h) * Korig + k];
    __nv_bfloat16 hi = __float2bfloat16(v);
    __nv_bfloat16 lo = __float2bfloat16(v - __bfloat162float(hi));
    size_t base = (size_t)n * (3 * Korig);
    dst[base + k] = hi;                 // pairs A_hi
    dst[base + Korig + k] = lo;         // pairs A_hi
    dst[base + 2 * Korig + k] = hi;     // pairs A_lo
}
__global__ void k_conv_bias(const float* __restrict__ bih, const float* __restrict__ bhh,
                            float* __restrict__ bp) {
    int n = blockIdx.x * blockDim.x + threadIdx.x;
    if (n >= G4) return;
    int h = n >> 2, g = n & 3;
    bp[n] = bih[g * Hh + h] + bhh[g * Hh + h];
}
__global__ void k_conv_x(const float* __restrict__ x) {
    int idx = blockIdx.x * blockDim.x + threadIdx.x;
    if (idx >= MTOT * NINp) return;
    int m = idx >> 6, k = idx & 63;
    int b = m & (Bb - 1), t = m >> 8;
    float v = x[((size_t)b * Tt + t) * NINp + k];
    __nv_bfloat16 hi = __float2bfloat16(v);
    g_xHi[idx] = hi;
    g_xLo[idx] = __float2bfloat16(v - __bfloat162float(hi));
}
__global__ void k_zero32(uint32_t* __restrict__ p, int n) {
    int i = blockIdx.x * blockDim.x + threadIdx.x;
    if (i < n) p[i] = 0u;
}
__global__ void k_final_c(const float* __restrict__ cT, float* __restrict__ dst) {
    int idx = blockIdx.x * blockDim.x + threadIdx.x;
    if (idx >= Bb * Hh) return;
    int b = idx >> 10, h = idx & (Hh - 1);
    dst[idx] = cT[(size_t)h * Bb + b];
}

// ------------------------- host launcher -----------------------------------
extern "C" void kernel_launch(void* const* d_in, const int* in_sizes, int n_in,
                              void* d_out, int out_size) {
    const float* x = (const float*)d_in[0];
    const float* Wih[4] = {(const float*)d_in[1], (const float*)d_in[5],
                           (const float*)d_in[9], (const float*)d_in[13]};
    const float* Whh[4] = {(const float*)d_in[2], (const float*)d_in[6],
                           (const float*)d_in[10], (const float*)d_in[14]};
    const float* bih[4] = {(const float*)d_in[3], (const float*)d_in[7],
                           (const float*)d_in[11], (const float*)d_in[15]};
    const float* bhh[4] = {(const float*)d_in[4], (const float*)d_in[8],
                           (const float*)d_in[12], (const float*)d_in[16]};
    float* out = (float*)d_out;

    __nv_bfloat16 *wihP, *whhP, *xHi, *xLo, *zbuf;
    __nv_bfloat16 *aAHi, *aALo, *aBHi, *aBLo;
    float *biasP, *gin, *cT;
    cudaGetSymbolAddress((void**)&wihP,  g_WihP);
    cudaGetSymbolAddress((void**)&whhP,  g_WhhP);
    cudaGetSymbolAddress((void**)&biasP, g_biasP);
    cudaGetSymbolAddress((void**)&gin,   g_gin);
    cudaGetSymbolAddress((void**)&aAHi,  g_actAHi);
    cudaGetSymbolAddress((void**)&aALo,  g_actALo);
    cudaGetSymbolAddress((void**)&aBHi,  g_actBHi);
    cudaGetSymbolAddress((void**)&aBLo,  g_actBLo);
    cudaGetSymbolAddress((void**)&xHi,   g_xHi);
    cudaGetSymbolAddress((void**)&xLo,   g_xLo);
    cudaGetSymbolAddress((void**)&zbuf,  g_zero);
    cudaGetSymbolAddress((void**)&cT,    g_cT);

    const int DSMEM_IN   = 65536 + 1024;
    const int DSMEM_STEP = 49152 + 1024;
    cudaFuncSetAttribute(k_gemm_in, cudaFuncAttributeMaxDynamicSharedMemorySize, DSMEM_IN);
    cudaFuncSetAttribute(k_step,    cudaFuncAttributeMaxDynamicSharedMemorySize, DSMEM_STEP);

    // weight / bias / input conversion (W' = [hi | lo | hi], rows permuted h*4+g)
    for (int L = 0; L < 4; L++) {
        int K = (L == 0) ? NINp : Hh;
        k_conv_w<<<(G4 * K + 255) / 256, 256>>>(Wih[L], wihP + (size_t)L * G4 * K3MAX, K);
        k_conv_w<<<(G4 * Hh + 255) / 256, 256>>>(Whh[L], whhP + (size_t)L * G4 * K3MAX, Hh);
        k_conv_bias<<<(G4 + 255) / 256, 256>>>(bih[L], bhh[L], biasP + L * G4);
    }
    k_conv_x<<<(MTOT * NINp + 255) / 256, 256>>>(x);
    k_zero32<<<(Bb * Hh * 2 / 4 + 255) / 256, 256>>>((uint32_t*)zbuf, Bb * Hh * 2 / 4);

    const __nv_bfloat16* inHi[4]  = {xHi, aAHi, aBHi, aAHi};
    const __nv_bfloat16* inLo[4]  = {xLo, aALo, aBLo, aALo};
    __nv_bfloat16*       outHi[4] = {aAHi, aBHi, aAHi, aBHi};
    __nv_bfloat16*       outLo[4] = {aALo, aBLo, aALo, aBLo};
    const int Ks[4] = {NINp, Hh, Hh, Hh};

    for (int L = 0; L < 4; L++) {
        k_zero32<<<(Hh * Bb + 255) / 256, 256>>>((uint32_t*)cT, Hh * Bb);

        dim3 ggrid(G4 / 128, MTOT / 128);
        k_gemm_in<<<ggrid, 256, DSMEM_IN>>>(inHi[L], inLo[L], Ks[L],
                                            wihP + (size_t)L * G4 * K3MAX,
                                            biasP + L * G4, gin);

        dim3 rgrid(G4 / 64, Bb / 128);
        for (int t = 0; t < Tt; t++) {
            const __nv_bfloat16* hHi = t ? (outHi[L] + (size_t)(t - 1) * Bb * Hh) : zbuf;
            const __nv_bfloat16* hLo = t ? (outLo[L] + (size_t)(t - 1) * Bb * Hh) : zbuf;
            k_step<<<rgrid, 256, DSMEM_STEP>>>(hHi, hLo,
                                               whhP + (size_t)L * G4 * K3MAX,
                                               gin, cT, outHi[L], outLo[L],
                                               (L == 3) ? out : nullptr, t);
        }
    }
    k_final_c<<<(Bb * Hh + 255) / 256, 256>>>(cT, out + (size_t)Bb * Tt * Hh);
}

// round 6
// speedup vs baseline: 3.7668x; 1.2765x over previous
#include <cuda_runtime.h>
#include <cuda_bf16.h>
#include <math.h>
#include <stdint.h>

#define Bb 256
#define Tt 100
#define NINp 64
#define Hh 1024
#define G4 4096
#define MTOT (Bb*Tt)
#define K2MAX (2*Hh)

// ------------------------- device scratch ----------------------------------
__device__ __align__(128) __nv_bfloat16 g_WihP[4][(size_t)G4 * K2MAX];
__device__ __align__(128) __nv_bfloat16 g_WhhP[4][(size_t)G4 * K2MAX];
__device__ __align__(128) float         g_biasP[4][G4];
__device__ __align__(128) float         g_gin[(size_t)MTOT * G4];
__device__ __align__(128) __nv_bfloat16 g_actAHi[(size_t)MTOT * Hh];
__device__ __align__(128) __nv_bfloat16 g_actALo[(size_t)MTOT * Hh];
__device__ __align__(128) __nv_bfloat16 g_actBHi[(size_t)MTOT * Hh];
__device__ __align__(128) __nv_bfloat16 g_actBLo[(size_t)MTOT * Hh];
__device__ __align__(128) __nv_bfloat16 g_xHi[(size_t)MTOT * NINp];
__device__ __align__(128) __nv_bfloat16 g_xLo[(size_t)MTOT * NINp];
__device__ __align__(128) __nv_bfloat16 g_zero[Bb * Hh];
__device__ __align__(128) float         g_cT[Hh * Bb];

// ------------------------- asm helpers -------------------------------------
__device__ __forceinline__ uint32_t smem_u32(const void* p) {
    uint32_t a;
    asm("{ .reg .u64 t; cvta.to.shared.u64 t, %1; cvt.u32.u64 %0, t; }" : "=r"(a) : "l"(p));
    return a;
}
#define CP16(s, g)  asm volatile("cp.async.cg.shared.global [%0], [%1], 16;" :: "r"(s), "l"(g) : "memory")
#define CP_COMMIT() asm volatile("cp.async.commit_group;" ::: "memory")
#define CP_WAIT1()  asm volatile("cp.async.wait_group 1;" ::: "memory")
#define CP_WAIT0()  asm volatile("cp.async.wait_group 0;" ::: "memory")
#define LDSM_X4(r, addr) asm volatile( \
    "ldmatrix.sync.aligned.m8n8.x4.shared.b16 {%0,%1,%2,%3}, [%4];" \
    : "=r"((r)[0]), "=r"((r)[1]), "=r"((r)[2]), "=r"((r)[3]) : "r"(addr))
#define MMA16816(d, a, b) asm volatile( \
    "mma.sync.aligned.m16n8k16.row.col.f32.bf16.bf16.f32 " \
    "{%0,%1,%2,%3}, {%4,%5,%6,%7}, {%8,%9}, {%0,%1,%2,%3};" \
    : "+f"((d)[0]), "+f"((d)[1]), "+f"((d)[2]), "+f"((d)[3]) \
    : "r"((a)[0]), "r"((a)[1]), "r"((a)[2]), "r"((a)[3]), "r"((b)[0]), "r"((b)[1]))

__device__ __forceinline__ float tanh_fast(float x) {
    float y;
    asm("tanh.approx.f32 %0, %1;" : "=f"(y) : "f"(x));
    return y;
}
__device__ __forceinline__ float sigf(float x) { return fmaf(tanh_fast(0.5f * x), 0.5f, 0.5f); }

// ------------------------- GEMM core ---------------------------------------
// acc[BMxBN] = (Ahi+Alo)[arow0.., K] x (Whi+Wlo)[n0.., K]^T  (3-term, lo*lo dropped)
// W stored as [hi | lo] (2K cols). BK=64, 3-stage cp.async pipeline, 1 sync/iter.
// 8 warps (2m x 4n), warp tile 64 x BN/4.
template<int BN>
__device__ __forceinline__ void load_stage(
    const __nv_bfloat16* __restrict__ Ahi, const __nv_bfloat16* __restrict__ Alo,
    int Korig, int arow0, const __nv_bfloat16* __restrict__ Wp, int n0,
    int it, uint32_t smBase, int tid)
{
    const int STAGE = 32768 + BN * 256;
    int kb = it << 6;
    uint32_t stg = smBase + (it % 3) * STAGE;
    size_t K2 = (size_t)(2 * Korig);
    #pragma unroll
    for (int i = 0; i < 4; i++) {                  // A hi+lo: 128 rows x 8 chunks each
        int u = tid + (i << 8);
        int row = u >> 3, kc = u & 7;
        size_t go = (size_t)(arow0 + row) * Korig + kb + kc * 8;
        uint32_t off = row * 128 + ((kc ^ (row & 7)) << 4);
        CP16(stg + off, (const void*)(Ahi + go));
        CP16(stg + 16384 + off, (const void*)(Alo + go));
    }
    #pragma unroll
    for (int i = 0; i < (BN >> 5); i++) {          // B hi+lo: BN rows x 8 chunks each
        int u = tid + (i << 8);
        int row = u >> 3, kc = u & 7;
        size_t gh = (size_t)(n0 + row) * K2 + kb + kc * 8;
        uint32_t off = row * 128 + ((kc ^ (row & 7)) << 4);
        CP16(stg + 32768 + off, (const void*)(Wp + gh));
        CP16(stg + 32768 + BN * 128 + off, (const void*)(Wp + gh + Korig));
    }
}

template<int BN>
__device__ __forceinline__ void compute_stage(
    int st, uint32_t smBase, int lane, int wm, int wn,
    float (&acc)[4][BN/32][4])
{
    const int STAGE = 32768 + BN * 256;
    uint32_t aHi = smBase + st * STAGE;
    uint32_t aLo = aHi + 16384;
    uint32_t bHi = aHi + 32768;
    uint32_t bLo = bHi + BN * 128;
    #pragma unroll
    for (int k16 = 0; k16 < 4; k16++) {
        int kc = k16 * 2 + (lane >> 4);
        uint32_t ah[4][4], al[4][4];
        #pragma unroll
        for (int fm = 0; fm < 4; fm++) {
            int row = wm * 64 + fm * 16 + (lane & 15);
            uint32_t off = row * 128 + ((kc ^ (row & 7)) << 4);
            LDSM_X4(ah[fm], aHi + off);
            LDSM_X4(al[fm], aLo + off);
        }
        uint32_t bh[BN/32][2], bl[BN/32][2];
        #pragma unroll
        for (int fp = 0; fp < BN/64; fp++) {
            int row = wn * (BN/4) + fp * 16 + (lane & 15);
            uint32_t off = row * 128 + ((kc ^ (row & 7)) << 4);
            uint32_t r[4];
            LDSM_X4(r, bHi + off);
            bh[fp*2][0] = r[0]; bh[fp*2+1][0] = r[1];
            bh[fp*2][1] = r[2]; bh[fp*2+1][1] = r[3];
            LDSM_X4(r, bLo + off);
            bl[fp*2][0] = r[0]; bl[fp*2+1][0] = r[1];
            bl[fp*2][1] = r[2]; bl[fp*2+1][1] = r[3];
        }
        #pragma unroll
        for (int fm = 0; fm < 4; fm++)
            #pragma unroll
            for (int fn = 0; fn < BN/32; fn++) {
                MMA16816(acc[fm][fn], ah[fm], bh[fn]);
                MMA16816(acc[fm][fn], ah[fm], bl[fn]);
                MMA16816(acc[fm][fn], al[fm], bh[fn]);
            }
    }
}

template<int BN>
__device__ __forceinline__ void gemm_core(
    const __nv_bfloat16* __restrict__ Ahi, const __nv_bfloat16* __restrict__ Alo,
    int Korig, int arow0, const __nv_bfloat16* __restrict__ Wp, int n0,
    char* sm, float (&acc)[4][BN/32][4])
{
    const int tid = threadIdx.x;
    const int lane = tid & 31, wid = tid >> 5;
    const int wm = wid & 1, wn = wid >> 1;
    const uint32_t smBase = smem_u32(sm);

    #pragma unroll
    for (int fm = 0; fm < 4; fm++)
        #pragma unroll
        for (int fn = 0; fn < BN/32; fn++)
            #pragma unroll
            for (int i = 0; i < 4; i++) acc[fm][fn][i] = 0.f;

    const int NIT = Korig >> 6;
    load_stage<BN>(Ahi, Alo, Korig, arow0, Wp, n0, 0, smBase, tid);
    CP_COMMIT();
    if (NIT > 1) {
        load_stage<BN>(Ahi, Alo, Korig, arow0, Wp, n0, 1, smBase, tid);
        CP_COMMIT();
    }
    #pragma unroll 1
    for (int it = 0; it < NIT; it++) {
        if (it < NIT - 1) { CP_WAIT1(); } else { CP_WAIT0(); }
        __syncthreads();
        compute_stage<BN>(it % 3, smBase, lane, wm, wn, acc);
        if (it + 2 < NIT) {
            load_stage<BN>(Ahi, Alo, Korig, arow0, Wp, n0, it + 2, smBase, tid);
            CP_COMMIT();
        }
    }
    __syncthreads();   // protect SMEM reuse by epilogues
}

// ------------------------- input GEMM --------------------------------------
__global__ void __launch_bounds__(256) k_gemm_in(
    const __nv_bfloat16* __restrict__ Ahi, const __nv_bfloat16* __restrict__ Alo, int Korig,
    const __nv_bfloat16* __restrict__ Wp, const float* __restrict__ biasP,
    float* __restrict__ gin)
{
    extern __shared__ char raw[];
    char* sm = (char*)(((uintptr_t)raw + 1023) & ~(uintptr_t)1023);
    int n0 = blockIdx.x * 128, m0 = blockIdx.y * 128;
    float acc[4][4][4];
    gemm_core<128>(Ahi, Alo, Korig, m0, Wp, n0, sm, acc);

    int tid = threadIdx.x, lane = tid & 31, wid = tid >> 5, wm = wid & 1, wn = wid >> 1;
    #pragma unroll
    for (int fm = 0; fm < 4; fm++) {
        int r0 = m0 + wm * 64 + fm * 16 + (lane >> 2);
        #pragma unroll
        for (int fn = 0; fn < 4; fn++) {
            int cg = n0 + wn * 32 + fn * 8 + (lane & 3) * 2;
            float2 bs = *(const float2*)&biasP[cg];
            float2 v0 = make_float2(acc[fm][fn][0] + bs.x, acc[fm][fn][1] + bs.y);
            float2 v1 = make_float2(acc[fm][fn][2] + bs.x, acc[fm][fn][3] + bs.y);
            *(float2*)&gin[(size_t)r0 * G4 + cg] = v0;
            *(float2*)&gin[((size_t)r0 + 8) * G4 + cg] = v1;
        }
    }
}

// ------------------------- recurrent step ----------------------------------
__global__ void __launch_bounds__(256) k_step(
    const __nv_bfloat16* __restrict__ hHi, const __nv_bfloat16* __restrict__ hLo,
    const __nv_bfloat16* __restrict__ Wp,
    const float* __restrict__ gin, float* __restrict__ cT,
    __nv_bfloat16* __restrict__ aoHi, __nv_bfloat16* __restrict__ aoLo,
    float* __restrict__ outp, int t)
{
    extern __shared__ char raw[];
    char* sm = (char*)(((uintptr_t)raw + 1023) & ~(uintptr_t)1023);
    int n0 = blockIdx.x * 64, m0 = blockIdx.y * 128;
    float acc[4][2][4];
    gemm_core<64>(hHi, hLo, Hh, m0, Wp, n0, sm, acc);

    int tid = threadIdx.x, lane = tid & 31, wid = tid >> 5, wm = wid & 1, wn = wid >> 1;
    float* s_out = (float*)sm;                           // [128][16] = 8KB
    __nv_bfloat16* s_hi = (__nv_bfloat16*)(sm + 8192);   // 4KB
    __nv_bfloat16* s_lo = (__nv_bfloat16*)(sm + 12288);  // 4KB
    int hb_cta = blockIdx.x * 16;

    #pragma unroll
    for (int fm = 0; fm < 4; fm++) {
        int rbase = wm * 64 + fm * 16 + (lane >> 2);
        #pragma unroll
        for (int fn = 0; fn < 2; fn++) {
            float d0 = acc[fm][fn][0], d1 = acc[fm][fn][1];
            float d2 = acc[fm][fn][2], d3 = acc[fm][fn][3];
            float p0 = __shfl_xor_sync(0xFFFFFFFFu, d0, 1);
            float p1 = __shfl_xor_sync(0xFFFFFFFFu, d1, 1);
            float p2 = __shfl_xor_sync(0xFFFFFFFFu, d2, 1);
            float p3 = __shfl_xor_sync(0xFFFFFFFFu, d3, 1);
            // even lane -> row rbase, has (i,f); odd lane -> row rbase+8, has (g,o)
            int r = rbase + ((lane & 1) ? 8 : 0);
            float xi, xf, xg, xo;
            if ((lane & 1) == 0) { xi = d0; xf = d1; xg = p0; xo = p1; }
            else                 { xi = p2; xf = p3; xg = d2; xo = d3; }
            int hl = wn * 4 + fn * 2 + ((lane & 3) >> 1);
            int b = m0 + r;
            const float* gr = gin + ((size_t)(t * Bb + b)) * G4 + n0 + hl * 4;
            float4 gv = *(const float4*)gr;
            xi += gv.x; xf += gv.y; xg += gv.z; xo += gv.w;
            float ig = sigf(xi), fg = sigf(xf), gg = tanh_fast(xg), og = sigf(xo);
            size_t ci = (size_t)(hb_cta + hl) * Bb + b;
            float cn = fg * cT[ci] + ig * gg;
            cT[ci] = cn;
            float hn = og * tanh_fast(cn);
            int si = r * 16 + hl;
            s_out[si] = hn;
            __nv_bfloat16 bh = __float2bfloat16(hn);
            s_hi[si] = bh;
            s_lo[si] = __float2bfloat16(hn - __bfloat162float(bh));
        }
    }
    __syncthreads();
    #pragma unroll
    for (int i = 0; i < 8; i++) {
        int u = tid + i * 256;
        int r = u >> 4, hl = u & 15;
        int b = m0 + r;
        size_t ai = ((size_t)(t * Bb + b)) * Hh + hb_cta + hl;
        aoHi[ai] = s_hi[u];
        aoLo[ai] = s_lo[u];
        if (outp) outp[((size_t)b * Tt + t) * Hh + hb_cta + hl] = s_out[u];
    }
}

// ------------------------- conversion / misc -------------------------------
__global__ void k_conv_w(const float* __restrict__ src, __nv_bfloat16* __restrict__ dst, int Korig) {
    int idx = blockIdx.x * blockDim.x + threadIdx.x;
    if (idx >= G4 * Korig) return;
    int n = idx / Korig, k = idx - n * Korig;
    int h = n >> 2, g = n & 3;
    float v = src[(size_t)(g * Hh + h) * Korig + k];
    __nv_bfloat16 hi = __float2bfloat16(v);
    __nv_bfloat16 lo = __float2bfloat16(v - __bfloat162float(hi));
    size_t base = (size_t)n * (2 * Korig);
    dst[base + k] = hi;
    dst[base + Korig + k] = lo;
}
__global__ void k_conv_bias(const float* __restrict__ bih, const float* __restrict__ bhh,
                            float* __restrict__ bp) {
    int n = blockIdx.x * blockDim.x + threadIdx.x;
    if (n >= G4) return;
    int h = n >> 2, g = n & 3;
    bp[n] = bih[g * Hh + h] + bhh[g * Hh + h];
}
__global__ void k_conv_x(const float* __restrict__ x) {
    int idx = blockIdx.x * blockDim.x + threadIdx.x;
    if (idx >= MTOT * NINp) return;
    int m = idx >> 6, k = idx & 63;
    int b = m & (Bb - 1), t = m >> 8;
    float v = x[((size_t)b * Tt + t) * NINp + k];
    __nv_bfloat16 hi = __float2bfloat16(v);
    g_xHi[idx] = hi;
    g_xLo[idx] = __float2bfloat16(v - __bfloat162float(hi));
}
__global__ void k_zero32(uint32_t* __restrict__ p, int n) {
    int i = blockIdx.x * blockDim.x + threadIdx.x;
    if (i < n) p[i] = 0u;
}
__global__ void k_final_c(const float* __restrict__ cT, float* __restrict__ dst) {
    int idx = blockIdx.x * blockDim.x + threadIdx.x;
    if (idx >= Bb * Hh) return;
    int b = idx >> 10, h = idx & (Hh - 1);
    dst[idx] = cT[(size_t)h * Bb + b];
}

// ------------------------- host launcher -----------------------------------
extern "C" void kernel_launch(void* const* d_in, const int* in_sizes, int n_in,
                              void* d_out, int out_size) {
    const float* x = (const float*)d_in[0];
    const float* Wih[4] = {(const float*)d_in[1], (const float*)d_in[5],
                           (const float*)d_in[9], (const float*)d_in[13]};
    const float* Whh[4] = {(const float*)d_in[2], (const float*)d_in[6],
                           (const float*)d_in[10], (const float*)d_in[14]};
    const float* bih[4] = {(const float*)d_in[3], (const float*)d_in[7],
                           (const float*)d_in[11], (const float*)d_in[15]};
    const float* bhh[4] = {(const float*)d_in[4], (const float*)d_in[8],
                           (const float*)d_in[12], (const float*)d_in[16]};
    float* out = (float*)d_out;

    __nv_bfloat16 *wihP, *whhP, *xHi, *xLo, *zbuf;
    __nv_bfloat16 *aAHi, *aALo, *aBHi, *aBLo;
    float *biasP, *gin, *cT;
    cudaGetSymbolAddress((void**)&wihP,  g_WihP);
    cudaGetSymbolAddress((void**)&whhP,  g_WhhP);
    cudaGetSymbolAddress((void**)&biasP, g_biasP);
    cudaGetSymbolAddress((void**)&gin,   g_gin);
    cudaGetSymbolAddress((void**)&aAHi,  g_actAHi);
    cudaGetSymbolAddress((void**)&aALo,  g_actALo);
    cudaGetSymbolAddress((void**)&aBHi,  g_actBHi);
    cudaGetSymbolAddress((void**)&aBLo,  g_actBLo);
    cudaGetSymbolAddress((void**)&xHi,   g_xHi);
    cudaGetSymbolAddress((void**)&xLo,   g_xLo);
    cudaGetSymbolAddress((void**)&zbuf,  g_zero);
    cudaGetSymbolAddress((void**)&cT,    g_cT);

    // stage = 32KB(A) + BN*256(B);   3 stages + 1KB alignment pad
    const int DSMEM_IN   = 3 * (32768 + 128 * 256) + 1024;  // 197632
    const int DSMEM_STEP = 3 * (32768 + 64 * 256)  + 1024;  // 148480
    cudaFuncSetAttribute(k_gemm_in, cudaFuncAttributeMaxDynamicSharedMemorySize, DSMEM_IN);
    cudaFuncSetAttribute(k_step,    cudaFuncAttributeMaxDynamicSharedMemorySize, DSMEM_STEP);

    // weight / bias / input conversion (W' = [hi | lo], rows permuted h*4+g)
    for (int L = 0; L < 4; L++) {
        int K = (L == 0) ? NINp : Hh;
        k_conv_w<<<(G4 * K + 255) / 256, 256>>>(Wih[L], wihP + (size_t)L * G4 * K2MAX, K);
        k_conv_w<<<(G4 * Hh + 255) / 256, 256>>>(Whh[L], whhP + (size_t)L * G4 * K2MAX, Hh);
        k_conv_bias<<<(G4 + 255) / 256, 256>>>(bih[L], bhh[L], biasP + L * G4);
    }
    k_conv_x<<<(MTOT * NINp + 255) / 256, 256>>>(x);
    k_zero32<<<(Bb * Hh * 2 / 4 + 255) / 256, 256>>>((uint32_t*)zbuf, Bb * Hh * 2 / 4);

    const __nv_bfloat16* inHi[4]  = {xHi, aAHi, aBHi, aAHi};
    const __nv_bfloat16* inLo[4]  = {xLo, aALo, aBLo, aALo};
    __nv_bfloat16*       outHi[4] = {aAHi, aBHi, aAHi, aBHi};
    __nv_bfloat16*       outLo[4] = {aALo, aBLo, aALo, aBLo};
    const int Ks[4] = {NINp, Hh, Hh, Hh};

    for (int L = 0; L < 4; L++) {
        k_zero32<<<(Hh * Bb + 255) / 256, 256>>>((uint32_t*)cT, Hh * Bb);

        dim3 ggrid(G4 / 128, MTOT / 128);
        k_gemm_in<<<ggrid, 256, DSMEM_IN>>>(inHi[L], inLo[L], Ks[L],
                                            wihP + (size_t)L * G4 * K2MAX,
                                            biasP + L * G4, gin);

        dim3 rgrid(G4 / 64, Bb / 128);
        for (int t = 0; t < Tt; t++) {
            const __nv_bfloat16* hHi = t ? (outHi[L] + (size_t)(t - 1) * Bb * Hh) : zbuf;
            const __nv_bfloat16* hLo = t ? (outLo[L] + (size_t)(t - 1) * Bb * Hh) : zbuf;
            k_step<<<rgrid, 256, DSMEM_STEP>>>(hHi, hLo,
                                               whhP + (size_t)L * G4 * K2MAX,
                                               gin, cT, outHi[L], outLo[L],
                                               (L == 3) ? out : nullptr, t);
        }
    }
    k_final_c<<<(Bb * Hh + 255) / 256, 256>>>(cT, out + (size_t)Bb * Tt * Hh);
}